// round 13
// baseline (speedup 1.0000x reference)
#include <cuda_runtime.h>
#include <cuda_bf16.h>
#include <cstdint>
#include <cstddef>
#include <math.h>

namespace g {
constexpr int B = 32, A = 4, NPER = 2048, N = 8192, DIN = 1024, OUTD = 11;
constexpr int KTOT   = N + DIN;              // 9216
constexpr int KSPLIT = 9;                    // kh 0..7 = Wsyn, kh 8 = Wrec
constexpr int KPART  = 1024;
constexpr int KC     = 32;
constexpr int MT     = 256;                  // rows per CTA (8 warps x 32 rows)
constexpr int NCH    = KPART / KC;           // 32
constexpr int STAGES = 3;
constexpr float THRESH = 0.05f;
constexpr float GTOT  = (float)(B * NPER);

constexpr int A_FLOATS = MT * 32;            // 8192 floats (32 KB), xor-swizzled
constexpr int BSTR = 40;                     // B row stride floats
constexpr int B_FLOATS = KC * BSTR;          // 1280 floats (5 KB)
constexpr int STAGE_F = A_FLOATS + B_FLOATS; // 9472
constexpr int STAGE_BYTES = STAGE_F * 4;     // 37888
constexpr int SM_TOTAL = STAGES * STAGE_BYTES;  // 113664 -> 2 CTAs/SM
}

// ------------------ device scratch ------------------
__device__ float g_gpart[64];                               // gate partials
__device__ int   g_perm[g::N];
__device__ float g_Ueff[(size_t)g::A * g::N * g::B];        // [o][c][b], 4 MB
__device__ float g_Xt[(size_t)g::DIN * g::B];               // [k][b]
__device__ float g_Woutp[(size_t)g::OUTD * g::N];           // Wout gathered by perm
__device__ float g_biasp[g::N];                             // gate*bsyn[p]+brec[p]
__device__ float g_part[(size_t)g::KSPLIT * g::N * g::B];   // [kh][b][j], 9 MB
__device__ float g_Zp[(size_t)g::B * g::N];                 // Z perm order [b][j]

// ------------------ helpers ------------------
__device__ __forceinline__ uint32_t smem_u32(const void* p) {
    uint32_t a;
    asm("{ .reg .u64 t; cvta.to.shared.u64 t, %1; cvt.u32.u64 %0, t; }" : "=r"(a) : "l"(p));
    return a;
}
__device__ __forceinline__ void cp16(uint32_t dst, const void* src) {
    asm volatile("cp.async.cg.shared.global [%0], [%1], 16;" :: "r"(dst), "l"(src) : "memory");
}
#define CP_COMMIT() asm volatile("cp.async.commit_group;" ::: "memory")
#define CP_WAIT1()  asm volatile("cp.async.wait_group 1;" ::: "memory")

__device__ __forceinline__ float rna_tf32(float v) {
    float r;
    asm("cvt.rna.tf32.f32 %0, %1;" : "=f"(r) : "f"(v));
    return r;
}
__device__ __forceinline__ uint32_t cvt_tf32_bits(float v) {
    uint32_t r;
    asm("cvt.rna.tf32.f32 %0, %1;" : "=r"(r) : "f"(v));
    return r;
}
__device__ __forceinline__ void mma_tf32(float& d0, float& d1, float& d2, float& d3,
                                         uint32_t a0, uint32_t a1, uint32_t a2, uint32_t a3,
                                         uint32_t b0, uint32_t b1) {
    asm volatile(
        "mma.sync.aligned.m16n8k8.row.col.f32.tf32.tf32.f32 "
        "{%0,%1,%2,%3}, {%4,%5,%6,%7}, {%8,%9}, {%0,%1,%2,%3};"
        : "+f"(d0), "+f"(d1), "+f"(d2), "+f"(d3)
        : "r"(a0), "r"(a1), "r"(a2), "r"(a3), "r"(b0), "r"(b1));
}
__device__ __forceinline__ float gate_of(int a) {
    float s = 0.f;
#pragma unroll
    for (int i = 0; i < 16; i++) s += g_gpart[a * 16 + i];
    return (s > g::THRESH * g::GTOT) ? 1.f : 0.f;
}

// =========================================================================
// 1) k_pre: blk 0 decode perm; blks 1..64 gate partials; blks 65..96 Xt.
//    All three groups are independent -> run concurrently in one launch.
//    Decode detection is OOB-safe: only odd words with index < N/2 (valid
//    in both int32 and int64 layouts) are examined.
// =========================================================================
__global__ void k_pre(const void* area_idx_raw, const float* __restrict__ Z0,
                      const float* __restrict__ x) {
    const int t = threadIdx.x;  // 256
    const int blk = blockIdx.x;
    if (blk == 0) {
        const unsigned* w32 = (const unsigned*)area_idx_raw;
        unsigned acc = 0;
        for (int i = t; i < g::N / 2; i += 256) acc |= w32[2 * i + 1];
        for (int o = 16; o; o >>= 1) acc |= __shfl_xor_sync(0xFFFFFFFFu, acc, o);
        __shared__ unsigned red[8];
        __shared__ int is64_s;
        if ((t & 31) == 0) red[t >> 5] = acc;
        __syncthreads();
        if (t == 0) {
            unsigned v = 0;
#pragma unroll
            for (int i = 0; i < 8; i++) v |= red[i];
            is64_s = (v == 0u) ? 1 : 0;
        }
        __syncthreads();
        const bool is64 = (is64_s != 0);
        const long long* p64 = (const long long*)area_idx_raw;
        const int*       p32 = (const int*)area_idx_raw;
        for (int i = t; i < g::N; i += 256)
            g_perm[i] = is64 ? (int)p64[i] : p32[i];
    } else if (blk <= 64) {
        int a  = (blk - 1) >> 4;
        int sl = (blk - 1) & 15;
        int b  = t >> 3;
        int m0 = sl * 128 + (t & 7) * 16;
        const float* src = Z0 + ((size_t)b * g::A + a) * g::NPER + m0;
        float s = 0.f;
#pragma unroll
        for (int i = 0; i < 16; i++) s += fabsf(src[i]);
        for (int o = 16; o; o >>= 1) s += __shfl_xor_sync(0xFFFFFFFFu, s, o);
        __shared__ float red[8];
        if ((t & 31) == 0) red[t >> 5] = s;
        __syncthreads();
        if (t == 0) {
            float tot = 0.f;
#pragma unroll
            for (int i = 0; i < 8; i++) tot += red[i];
            g_gpart[blk - 1] = tot;
        }
    } else {
        __shared__ float sm[32][33];
        int w = t >> 5, l = t & 31;
        int k0 = (blk - 65) * 32;
#pragma unroll
        for (int bi = 0; bi < 4; bi++) {
            int b = w + 8 * bi;
            sm[b][l] = x[(size_t)b * g::DIN + k0 + l];
        }
        __syncthreads();
#pragma unroll
        for (int ji = 0; ji < 4; ji++) {
            int kloc = w + 8 * ji;
            g_Xt[((size_t)(k0 + kloc) << 5) + l] = rna_tf32(sm[l][kloc]);
        }
    }
}

// =========================================================================
// 2) k_build: blks 0..255 Ueff; 256..266 Woutp gather; 267..270 biasp
// =========================================================================
__global__ void k_build(const float* __restrict__ Z0, const float* __restrict__ Wout,
                        const float* __restrict__ bsyn, const float* __restrict__ brec) {
    int t = threadIdx.x;
    int blk = blockIdx.x;
    if (blk < 256) {
        __shared__ float sm[32][33];
        int w = t >> 5, l = t & 31;
        int j0 = blk * 32;
        int a  = j0 >> 11;
        int m0 = j0 & (g::NPER - 1);
#pragma unroll
        for (int bi = 0; bi < 4; bi++) {
            int b = w + 8 * bi;
            sm[b][l] = Z0[((size_t)b * g::A + a) * g::NPER + m0 + l];
        }
        __syncthreads();
        float gate = gate_of(a);
#pragma unroll
        for (int ji = 0; ji < 4; ji++) {
            int jloc = w + 8 * ji;
            int c = g_perm[j0 + jloc];
            float zg = sm[l][jloc] * gate;
#pragma unroll
            for (int o = 0; o < g::A; o++) {
                float sc = (o == a) ? 0.8f : 0.1f;
                g_Ueff[(((size_t)o * g::N + c) << 5) + l] = rna_tf32(sc * zg);
            }
        }
    } else if (blk < 256 + g::OUTD) {
        int tt = blk - 256;
        const float* wrow = Wout + (size_t)tt * g::N;
        float* dstw = g_Woutp + (size_t)tt * g::N;
        for (int j = t; j < g::N; j += 256) dstw[j] = wrow[g_perm[j]];
    } else {
        int base = (blk - 256 - g::OUTD) * 2048;
#pragma unroll
        for (int i = 0; i < 8; i++) {
            int j = base + t + i * 256;
            int rp = g_perm[j];
            float gate = gate_of(j >> 11);
            g_biasp[j] = gate * bsyn[rp] + brec[rp];
        }
    }
}

// =========================================================================
// 3) main GEMM via mma.sync tf32 (PROVEN config — unchanged).
//    grid (32, 9), 256 threads, 3 stages, wait_group 1, 2 CTAs/SM.
// =========================================================================
__global__ void __launch_bounds__(256) k_main(const float* __restrict__ Wsyn,
                                              const float* __restrict__ Wrec) {
    extern __shared__ float smem[];
    __shared__ int srow[g::MT];
    const uint32_t su = smem_u32(smem);

    const int tid = threadIdx.x, wid = tid >> 5, lane = tid & 31;
    const int gq = lane >> 2, tq = lane & 3;
    const int j0 = blockIdx.x * g::MT;
    const int kh = blockIdx.y;
    const bool rec = (kh == 8);
    const int kbase = rec ? 0 : kh * g::KPART;
    const char* wb = (const char*)(rec ? Wrec : Wsyn);
    const uint32_t ldb = rec ? (g::DIN * 4) : (g::N * 4);

    srow[tid] = g_perm[j0 + tid];
    __syncthreads();

    const int kg = tid & 7, rowb = tid >> 3;
    uint32_t aoff[8];
#pragma unroll
    for (int i = 0; i < 8; i++) aoff[i] = (uint32_t)srow[rowb + 32 * i] * ldb;
    const uint32_t dstAbase = su + rowb * 128 + ((kg ^ (rowb & 7)) * 16);
    const uint32_t colbyte = (uint32_t)kbase * 4 + kg * 16;
    const int krow = tid >> 3, ng = tid & 7;
    const char* bsrc = (const char*)(rec
        ? g_Xt + ((size_t)krow << 5) + ng * 4
        : g_Ueff + (((size_t)(blockIdx.x >> 3) * g::N + kbase + krow) << 5) + ng * 4);
    const uint32_t dstB = su + g::A_FLOATS * 4 + krow * (g::BSTR * 4) + ng * 16;

    auto issue = [&](int q) {
        const uint32_t so = (uint32_t)(q % g::STAGES) * g::STAGE_BYTES;
        const uint32_t cb = colbyte + (uint32_t)q * 128;
#pragma unroll
        for (int i = 0; i < 8; i++)
            cp16(dstAbase + so + i * 4096, wb + (size_t)aoff[i] + cb);
        cp16(dstB + so, bsrc + (size_t)q * 4096);
    };

    float acc[2][4][4];
#pragma unroll
    for (int mt = 0; mt < 2; mt++)
#pragma unroll
        for (int nt = 0; nt < 4; nt++)
#pragma unroll
            for (int c = 0; c < 4; c++) acc[mt][nt][c] = 0.f;

    for (int q = 0; q < g::STAGES - 1; q++) { issue(q); CP_COMMIT(); }

    const int xo = 4 * gq;

    for (int q = 0; q < g::NCH; q++) {
        CP_WAIT1();
        __syncthreads();
        if (q + g::STAGES - 1 < g::NCH) issue(q + g::STAGES - 1);
        CP_COMMIT();

        const float* As = smem + (q % g::STAGES) * g::STAGE_F;
        const float* Bs = As + g::A_FLOATS;
#pragma unroll
        for (int ks = 0; ks < 4; ks++) {
            const int kc = ks * 8 + tq;
            uint32_t b0[4], b1[4];
#pragma unroll
            for (int nt = 0; nt < 4; nt++) {
                b0[nt] = __float_as_uint(Bs[kc * g::BSTR + nt * 8 + gq]);
                b1[nt] = __float_as_uint(Bs[(kc + 4) * g::BSTR + nt * 8 + gq]);
            }
#pragma unroll
            for (int mt = 0; mt < 2; mt++) {
                const int r = wid * 32 + mt * 16 + gq;
                uint32_t a0 = cvt_tf32_bits(As[r * 32 + (kc ^ xo)]);
                uint32_t a1 = cvt_tf32_bits(As[(r + 8) * 32 + (kc ^ xo)]);
                uint32_t a2 = cvt_tf32_bits(As[r * 32 + ((kc + 4) ^ xo)]);
                uint32_t a3 = cvt_tf32_bits(As[(r + 8) * 32 + ((kc + 4) ^ xo)]);
#pragma unroll
                for (int nt = 0; nt < 4; nt++)
                    mma_tf32(acc[mt][nt][0], acc[mt][nt][1], acc[mt][nt][2], acc[mt][nt][3],
                             a0, a1, a2, a3, b0[nt], b1[nt]);
            }
        }
    }

    float* dst = g_part + (size_t)kh * ((size_t)g::N * g::B);
#pragma unroll
    for (int mt = 0; mt < 2; mt++) {
        const int jr = j0 + wid * 32 + mt * 16 + gq;
#pragma unroll
        for (int nt = 0; nt < 4; nt++) {
            int bc = nt * 8 + 2 * tq;
            dst[(size_t)bc * g::N + jr]           = acc[mt][nt][0];
            dst[(size_t)(bc + 1) * g::N + jr]     = acc[mt][nt][1];
            dst[(size_t)bc * g::N + jr + 8]       = acc[mt][nt][2];
            dst[(size_t)(bc + 1) * g::N + jr + 8] = acc[mt][nt][3];
        }
    }
}

// =========================================================================
// 4) k_final (float4): combine partials + biasp + tanh -> Zp[b][j]
// =========================================================================
__global__ void __launch_bounds__(256) k_final() {
    const size_t v4 = (size_t)blockIdx.x * 256 + threadIdx.x;  // float4 index
    const float4* P = (const float4*)g_part;
    constexpr size_t S4 = (size_t)g::N * g::B / 4;
    float4 v = P[v4];
#pragma unroll
    for (int kh = 1; kh < g::KSPLIT; kh++) {
        float4 p = P[v4 + kh * S4];
        v.x += p.x; v.y += p.y; v.z += p.z; v.w += p.w;
    }
    const float4 bp = ((const float4*)g_biasp)[v4 & (g::N / 4 - 1)];
    float4 z;
    z.x = tanhf(v.x + bp.x);
    z.y = tanhf(v.y + bp.y);
    z.z = tanhf(v.z + bp.z);
    z.w = tanhf(v.w + bp.w);
    ((float4*)g_Zp)[v4] = z;
}

// =========================================================================
// 5) k_out: coalesced Woutp . Zp
// =========================================================================
__global__ void k_out(const float* __restrict__ bout, float* __restrict__ out) {
    int tt = blockIdx.x, b = blockIdx.y, t = threadIdx.x;
    const float4* wrow = (const float4*)(g_Woutp + (size_t)tt * g::N);
    const float4* zrow = (const float4*)(g_Zp + (size_t)b * g::N);
    float s = 0.f;
    for (int q = t; q < g::N / 4; q += 256) {
        float4 w = wrow[q], z = zrow[q];
        s += w.x * z.x + w.y * z.y + w.z * z.z + w.w * z.w;
    }
    for (int o = 16; o; o >>= 1) s += __shfl_xor_sync(0xFFFFFFFFu, s, o);
    __shared__ float red[8];
    if ((t & 31) == 0) red[t >> 5] = s;
    __syncthreads();
    if (t == 0) {
        float tot = 0.f;
#pragma unroll
        for (int i = 0; i < 8; i++) tot += red[i];
        tot += bout[tt];
        if (tt < 10) out[(size_t)b * 10 + tt] = tot;
        else         out[320 + b] = 1.f / (1.f + expf(-tot));
    }
}

// =========================================================================
extern "C" void kernel_launch(void* const* d_in, const int* in_sizes, int n_in,
                              void* d_out, int out_size) {
    const float* x    = (const float*)d_in[0];
    const float* Z0   = (const float*)d_in[1];
    const float* Wrec = (const float*)d_in[2];
    const float* brec = (const float*)d_in[3];
    const float* Wsyn = (const float*)d_in[4];
    const float* bsyn = (const float*)d_in[5];
    const float* Wout = (const float*)d_in[6];
    const float* bout = (const float*)d_in[7];
    const void*  aidx = d_in[8];
    float* out = (float*)d_out;

    static bool attr_set = false;
    if (!attr_set) {
        cudaFuncSetAttribute(k_main, cudaFuncAttributeMaxDynamicSharedMemorySize, g::SM_TOTAL);
        attr_set = true;
    }

    k_pre<<<97, 256>>>(aidx, Z0, x);
    k_build<<<256 + g::OUTD + 4, 256>>>(Z0, Wout, bsyn, brec);
    k_main<<<dim3(g::N / g::MT, g::KSPLIT), 256, g::SM_TOTAL>>>(Wsyn, Wrec);
    k_final<<<((size_t)g::N * g::B) / 1024, 256>>>();
    k_out<<<dim3(g::OUTD, g::B), 256>>>(bout, out);
}

// round 14
// speedup vs baseline: 1.2579x; 1.2579x over previous
#include <cuda_runtime.h>
#include <cuda_bf16.h>
#include <cstdint>
#include <cstddef>
#include <math.h>

namespace g {
constexpr int B = 32, A = 4, NPER = 2048, N = 8192, DIN = 1024, OUTD = 11;
constexpr int KTOT   = N + DIN;              // 9216
constexpr int KSPLIT = 9;                    // kh 0..7 = Wsyn, kh 8 = Wrec
constexpr int KPART  = 1024;
constexpr int KC     = 32;
constexpr int MT     = 256;                  // rows per CTA (8 warps x 32 rows)
constexpr int NCH    = KPART / KC;           // 32
constexpr int STAGES = 3;
constexpr float THRESH = 0.05f;
constexpr float GTOT  = (float)(B * NPER);

constexpr int A_FLOATS = MT * 32;            // 8192 floats (32 KB), xor-swizzled
constexpr int BSTR = 40;                     // B row stride floats
constexpr int B_FLOATS = KC * BSTR;          // 1280 floats (5 KB)
constexpr int STAGE_F = A_FLOATS + B_FLOATS; // 9472
constexpr int STAGE_BYTES = STAGE_F * 4;     // 37888
constexpr int SM_TOTAL = STAGES * STAGE_BYTES;  // 113664 -> 2 CTAs/SM
}

// ------------------ device scratch ------------------
__device__ float g_gsum[g::A];
__device__ int   g_perm[g::N];
__device__ float g_Ueff[(size_t)g::A * g::N * g::B];        // [o][c][b], 4 MB
__device__ float g_Xt[(size_t)g::DIN * g::B];               // [k][b]
__device__ float g_acc[(size_t)g::N * g::B];                // [b][j], 1 MB (RED target)
__device__ float g_Zp[(size_t)g::B * g::N];                 // Z perm order [b][j]

// ------------------ helpers ------------------
__device__ __forceinline__ uint32_t smem_u32(const void* p) {
    uint32_t a;
    asm("{ .reg .u64 t; cvta.to.shared.u64 t, %1; cvt.u32.u64 %0, t; }" : "=r"(a) : "l"(p));
    return a;
}
__device__ __forceinline__ void cp16(uint32_t dst, const void* src) {
    asm volatile("cp.async.cg.shared.global [%0], [%1], 16;" :: "r"(dst), "l"(src) : "memory");
}
#define CP_COMMIT() asm volatile("cp.async.commit_group;" ::: "memory")
#define CP_WAIT1()  asm volatile("cp.async.wait_group 1;" ::: "memory")

__device__ __forceinline__ float rna_tf32(float v) {
    float r;
    asm("cvt.rna.tf32.f32 %0, %1;" : "=f"(r) : "f"(v));
    return r;
}
__device__ __forceinline__ uint32_t cvt_tf32_bits(float v) {
    uint32_t r;
    asm("cvt.rna.tf32.f32 %0, %1;" : "=r"(r) : "f"(v));
    return r;
}
__device__ __forceinline__ void mma_tf32(float& d0, float& d1, float& d2, float& d3,
                                         uint32_t a0, uint32_t a1, uint32_t a2, uint32_t a3,
                                         uint32_t b0, uint32_t b1) {
    asm volatile(
        "mma.sync.aligned.m16n8k8.row.col.f32.tf32.tf32.f32 "
        "{%0,%1,%2,%3}, {%4,%5,%6,%7}, {%8,%9}, {%0,%1,%2,%3};"
        : "+f"(d0), "+f"(d1), "+f"(d2), "+f"(d3)
        : "r"(a0), "r"(a1), "r"(a2), "r"(a3), "r"(b0), "r"(b1));
}

// =========================================================================
// 1) decode area_idx (int32 or int64) -> g_perm; zero gate sums.
//    OOB-safe detection: only odd words with index < N/2.
// =========================================================================
__global__ void k_decode(const void* area_idx_raw) {
    const unsigned* w32 = (const unsigned*)area_idx_raw;
    int t = threadIdx.x;  // 1024
    if (t < g::A) g_gsum[t] = 0.f;
    unsigned acc = 0;
    for (int i = t; i < g::N / 2; i += 1024) acc |= w32[2 * i + 1];
    for (int o = 16; o; o >>= 1) acc |= __shfl_xor_sync(0xFFFFFFFFu, acc, o);
    __shared__ unsigned red[32];
    __shared__ int is64_s;
    if ((t & 31) == 0) red[t >> 5] = acc;
    __syncthreads();
    if (t < 32) {
        unsigned v = red[t];
        for (int o = 16; o; o >>= 1) v |= __shfl_xor_sync(0xFFFFFFFFu, v, o);
        if (t == 0) is64_s = (v == 0u) ? 1 : 0;
    }
    __syncthreads();
    bool is64 = (is64_s != 0);
    const long long* p64 = (const long long*)area_idx_raw;
    const int*       p32 = (const int*)area_idx_raw;
    for (int i = t; i < g::N; i += 1024)
        g_perm[i] = is64 ? (int)p64[i] : p32[i];
}

// =========================================================================
// 2) gate partial sums (blocks 0..63) + zero g_acc (blocks 64..95)
// =========================================================================
__global__ void k_gate(const float* __restrict__ Z0) {
    int t = threadIdx.x;
    if (blockIdx.x >= 64) {
        float4* dst = (float4*)g_acc + ((size_t)(blockIdx.x - 64) * 256 + t) * 8;
        const float4 z4 = make_float4(0.f, 0.f, 0.f, 0.f);
#pragma unroll
        for (int i = 0; i < 8; i++) dst[i] = z4;
        return;
    }
    int a  = blockIdx.x >> 4;
    int sl = blockIdx.x & 15;
    int b  = t >> 3;
    int m0 = sl * 128 + (t & 7) * 16;
    const float* src = Z0 + ((size_t)b * g::A + a) * g::NPER + m0;
    float s = 0.f;
#pragma unroll
    for (int i = 0; i < 16; i++) s += fabsf(src[i]);
    for (int o = 16; o; o >>= 1) s += __shfl_xor_sync(0xFFFFFFFFu, s, o);
    __shared__ float red[8];
    if ((t & 31) == 0) red[t >> 5] = s;
    __syncthreads();
    if (t == 0) {
        float tot = 0.f;
#pragma unroll
        for (int i = 0; i < 8; i++) tot += red[i];
        atomicAdd(&g_gsum[a], tot);
    }
}

// =========================================================================
// 3) build Ueff / Xt with coalesced loads via smem transpose.
// =========================================================================
__global__ void k_build(const float* __restrict__ Z0, const float* __restrict__ x) {
    __shared__ float sm[32][33];
    int t = threadIdx.x, w = t >> 5, l = t & 31;
    int blk = blockIdx.x;
    if (blk < 256) {
        int j0 = blk * 32;
        int a  = j0 >> 11;
        int m0 = j0 & (g::NPER - 1);
#pragma unroll
        for (int bi = 0; bi < 4; bi++) {
            int b = w + 8 * bi;
            sm[b][l] = Z0[((size_t)b * g::A + a) * g::NPER + m0 + l];
        }
        __syncthreads();
        float gate = (g_gsum[a] > g::THRESH * g::GTOT) ? 1.f : 0.f;
#pragma unroll
        for (int ji = 0; ji < 4; ji++) {
            int jloc = w + 8 * ji;
            int c = g_perm[j0 + jloc];
            float zg = sm[l][jloc] * gate;
#pragma unroll
            for (int o = 0; o < g::A; o++) {
                float sc = (o == a) ? 0.8f : 0.1f;
                g_Ueff[(((size_t)o * g::N + c) << 5) + l] = rna_tf32(sc * zg);
            }
        }
    } else {
        int k0 = (blk - 256) * 32;
#pragma unroll
        for (int bi = 0; bi < 4; bi++) {
            int b = w + 8 * bi;
            sm[b][l] = x[(size_t)b * g::DIN + k0 + l];
        }
        __syncthreads();
#pragma unroll
        for (int ji = 0; ji < 4; ji++) {
            int kloc = w + 8 * ji;
            g_Xt[((size_t)(k0 + kloc) << 5) + l] = rna_tf32(sm[l][kloc]);
        }
    }
}

// =========================================================================
// 4) main GEMM via mma.sync tf32 (proven config). Epilogue: RED.ADD into
//    the single L2-resident accumulator g_acc (no partial buffers).
// =========================================================================
__global__ void __launch_bounds__(256) k_main(const float* __restrict__ Wsyn,
                                              const float* __restrict__ Wrec) {
    extern __shared__ float smem[];
    __shared__ int srow[g::MT];
    const uint32_t su = smem_u32(smem);

    const int tid = threadIdx.x, wid = tid >> 5, lane = tid & 31;
    const int gq = lane >> 2, tq = lane & 3;
    const int j0 = blockIdx.x * g::MT;
    const int kh = blockIdx.y;
    const bool rec = (kh == 8);
    const int kbase = rec ? 0 : kh * g::KPART;
    const char* wb = (const char*)(rec ? Wrec : Wsyn);
    const uint32_t ldb = rec ? (g::DIN * 4) : (g::N * 4);

    srow[tid] = g_perm[j0 + tid];
    __syncthreads();

    const int kg = tid & 7, rowb = tid >> 3;
    uint32_t aoff[8];
#pragma unroll
    for (int i = 0; i < 8; i++) aoff[i] = (uint32_t)srow[rowb + 32 * i] * ldb;
    const uint32_t dstAbase = su + rowb * 128 + ((kg ^ (rowb & 7)) * 16);
    const uint32_t colbyte = (uint32_t)kbase * 4 + kg * 16;
    const int krow = tid >> 3, ng = tid & 7;
    const char* bsrc = (const char*)(rec
        ? g_Xt + ((size_t)krow << 5) + ng * 4
        : g_Ueff + (((size_t)(blockIdx.x >> 3) * g::N + kbase + krow) << 5) + ng * 4);
    const uint32_t dstB = su + g::A_FLOATS * 4 + krow * (g::BSTR * 4) + ng * 16;

    auto issue = [&](int q) {
        const uint32_t so = (uint32_t)(q % g::STAGES) * g::STAGE_BYTES;
        const uint32_t cb = colbyte + (uint32_t)q * 128;
#pragma unroll
        for (int i = 0; i < 8; i++)
            cp16(dstAbase + so + i * 4096, wb + (size_t)aoff[i] + cb);
        cp16(dstB + so, bsrc + (size_t)q * 4096);
    };

    float acc[2][4][4];
#pragma unroll
    for (int mt = 0; mt < 2; mt++)
#pragma unroll
        for (int nt = 0; nt < 4; nt++)
#pragma unroll
            for (int c = 0; c < 4; c++) acc[mt][nt][c] = 0.f;

    for (int q = 0; q < g::STAGES - 1; q++) { issue(q); CP_COMMIT(); }

    const int xo = 4 * gq;

    for (int q = 0; q < g::NCH; q++) {
        CP_WAIT1();
        __syncthreads();
        if (q + g::STAGES - 1 < g::NCH) issue(q + g::STAGES - 1);
        CP_COMMIT();

        const float* As = smem + (q % g::STAGES) * g::STAGE_F;
        const float* Bs = As + g::A_FLOATS;
#pragma unroll
        for (int ks = 0; ks < 4; ks++) {
            const int kc = ks * 8 + tq;
            uint32_t b0[4], b1[4];
#pragma unroll
            for (int nt = 0; nt < 4; nt++) {
                b0[nt] = __float_as_uint(Bs[kc * g::BSTR + nt * 8 + gq]);
                b1[nt] = __float_as_uint(Bs[(kc + 4) * g::BSTR + nt * 8 + gq]);
            }
#pragma unroll
            for (int mt = 0; mt < 2; mt++) {
                const int r = wid * 32 + mt * 16 + gq;
                uint32_t a0 = cvt_tf32_bits(As[r * 32 + (kc ^ xo)]);
                uint32_t a1 = cvt_tf32_bits(As[(r + 8) * 32 + (kc ^ xo)]);
                uint32_t a2 = cvt_tf32_bits(As[r * 32 + ((kc + 4) ^ xo)]);
                uint32_t a3 = cvt_tf32_bits(As[(r + 8) * 32 + ((kc + 4) ^ xo)]);
#pragma unroll
                for (int nt = 0; nt < 4; nt++)
                    mma_tf32(acc[mt][nt][0], acc[mt][nt][1], acc[mt][nt][2], acc[mt][nt][3],
                             a0, a1, a2, a3, b0[nt], b1[nt]);
            }
        }
    }

    // epilogue: fire-and-forget RED.ADD into g_acc[b][j] (L2-resident)
#pragma unroll
    for (int mt = 0; mt < 2; mt++) {
        const int jr = j0 + wid * 32 + mt * 16 + gq;
#pragma unroll
        for (int nt = 0; nt < 4; nt++) {
            int bc = nt * 8 + 2 * tq;
            atomicAdd(&g_acc[(size_t)bc * g::N + jr],           acc[mt][nt][0]);
            atomicAdd(&g_acc[(size_t)(bc + 1) * g::N + jr],     acc[mt][nt][1]);
            atomicAdd(&g_acc[(size_t)bc * g::N + jr + 8],       acc[mt][nt][2]);
            atomicAdd(&g_acc[(size_t)(bc + 1) * g::N + jr + 8], acc[mt][nt][3]);
        }
    }
}

// =========================================================================
// 5) bias + tanh -> Zp[b][j]   (reads 1 MB accumulator, L2-hot)
// =========================================================================
__global__ void k_final(const float* __restrict__ bsyn, const float* __restrict__ brec) {
    size_t idx = (size_t)blockIdx.x * 256 + threadIdx.x;   // b*N + j
    int j = (int)(idx & (g::N - 1));
    int rp = g_perm[j];
    int o = j >> 11;
    float gate = (g_gsum[o] > g::THRESH * g::GTOT) ? 1.f : 0.f;
    float v = g_acc[idx] + gate * bsyn[rp] + brec[rp];
    g_Zp[idx] = tanhf(v);
}

// =========================================================================
// 6) output lobe
// =========================================================================
__global__ void k_out(const float* __restrict__ Wout, const float* __restrict__ bout,
                      float* __restrict__ out) {
    int tt = blockIdx.x, b = blockIdx.y, t = threadIdx.x;
    const float* wrow = Wout + (size_t)tt * g::N;
    const float* zrow = g_Zp + (size_t)b * g::N;
    float s = 0.f;
    for (int q = t; q < g::N; q += 256) s += wrow[g_perm[q]] * zrow[q];
    for (int o = 16; o; o >>= 1) s += __shfl_xor_sync(0xFFFFFFFFu, s, o);
    __shared__ float red[8];
    if ((t & 31) == 0) red[t >> 5] = s;
    __syncthreads();
    if (t == 0) {
        float tot = 0.f;
#pragma unroll
        for (int i = 0; i < 8; i++) tot += red[i];
        tot += bout[tt];
        if (tt < 10) out[(size_t)b * 10 + tt] = tot;
        else         out[320 + b] = 1.f / (1.f + expf(-tot));
    }
}

// =========================================================================
extern "C" void kernel_launch(void* const* d_in, const int* in_sizes, int n_in,
                              void* d_out, int out_size) {
    const float* x    = (const float*)d_in[0];
    const float* Z0   = (const float*)d_in[1];
    const float* Wrec = (const float*)d_in[2];
    const float* brec = (const float*)d_in[3];
    const float* Wsyn = (const float*)d_in[4];
    const float* bsyn = (const float*)d_in[5];
    const float* Wout = (const float*)d_in[6];
    const float* bout = (const float*)d_in[7];
    const void*  aidx = d_in[8];
    float* out = (float*)d_out;

    static bool attr_set = false;
    if (!attr_set) {
        cudaFuncSetAttribute(k_main, cudaFuncAttributeMaxDynamicSharedMemorySize, g::SM_TOTAL);
        attr_set = true;
    }

    k_decode<<<1, 1024>>>(aidx);
    k_gate<<<96, 256>>>(Z0);
    k_build<<<288, 256>>>(Z0, x);
    k_main<<<dim3(g::N / g::MT, g::KSPLIT), 256, g::SM_TOTAL>>>(Wsyn, Wrec);
    k_final<<<((size_t)g::N * g::B) / 256, 256>>>(bsyn, brec);
    k_out<<<dim3(g::OUTD, g::B), 256>>>(Wout, bout, out);
}